// round 6
// baseline (speedup 1.0000x reference)
#include <cuda_runtime.h>
#include <cuda_fp16.h>
#include <math.h>
#include <stdint.h>

#define B_ROWS 16384
#define D_DIM  2048
#define D_HALF 1024
#define S_PROTO 64
#define KCOMB  (D_DIM + S_PROTO)   // 2112

// ---------------------------------------------------------------------------
// Scratch (device globals; allocation-free per harness rules)
// ---------------------------------------------------------------------------
__device__ __half g_x_h[(size_t)B_ROWS * D_DIM];
__device__ __half g_Win_h[(size_t)D_DIM * D_DIM];
__device__ __half g_Wr1_h[(size_t)D_HALF * D_DIM];
__device__ __half g_wcomb[(size_t)D_DIM * KCOMB];      // [W_out1 | P2^T] fp16
__device__ __half g_attn_h[(size_t)B_ROWS * S_PROTO];
__device__ float g_h[(size_t)B_ROWS * D_DIM];
__device__ float g_r[(size_t)B_ROWS * D_HALF];
__device__ float g_tw[(size_t)B_ROWS * 4];
__device__ float g_pn[(size_t)S_PROTO * D_DIM];
__device__ float g_base[S_PROTO];
__device__ float g_wsimc[S_PROTO];

// ---------------------------------------------------------------------------
// PTX helpers (baseline ISA: mma.sync / ldmatrix / cp.async)
// ---------------------------------------------------------------------------
__device__ __forceinline__ uint32_t smem_to_u32(const void* p) {
    uint32_t a;
    asm("{ .reg .u64 t; cvta.to.shared.u64 t, %1; cvt.u32.u64 %0, t; }"
        : "=r"(a) : "l"(p));
    return a;
}

__device__ __forceinline__ void cpasync16(uint32_t saddr, const void* g) {
    asm volatile("cp.async.cg.shared.global [%0], [%1], 16;"
                 :: "r"(saddr), "l"(g));
}
#define CP_COMMIT() asm volatile("cp.async.commit_group;" ::: "memory")
#define CP_WAIT(n)  asm volatile("cp.async.wait_group %0;" :: "n"(n) : "memory")

__device__ __forceinline__ void ldsm4(uint32_t* r, uint32_t addr) {
    asm volatile("ldmatrix.sync.aligned.m8n8.x4.shared.b16 {%0,%1,%2,%3}, [%4];"
                 : "=r"(r[0]), "=r"(r[1]), "=r"(r[2]), "=r"(r[3]) : "r"(addr));
}

__device__ __forceinline__ void mma_f16(float* d, const uint32_t* a, const uint32_t* b) {
    asm volatile(
        "mma.sync.aligned.m16n8k16.row.col.f32.f16.f16.f32 "
        "{%0,%1,%2,%3}, {%4,%5,%6,%7}, {%8,%9}, {%0,%1,%2,%3};"
        : "+f"(d[0]), "+f"(d[1]), "+f"(d[2]), "+f"(d[3])
        : "r"(a[0]), "r"(a[1]), "r"(a[2]), "r"(a[3]), "r"(b[0]), "r"(b[1]));
}

// ---------------------------------------------------------------------------
// Misc helpers
// ---------------------------------------------------------------------------
__device__ __forceinline__ float gelu_exact(float v) {
    return 0.5f * v * (1.0f + erff(v * 0.70710678118654752440f));
}

__device__ __forceinline__ float block_reduce_sum(float v) {
    __shared__ float sh[32];
    int lane = threadIdx.x & 31, w = threadIdx.x >> 5;
    #pragma unroll
    for (int o = 16; o; o >>= 1) v += __shfl_xor_sync(0xFFFFFFFFu, v, o);
    if (lane == 0) sh[w] = v;
    __syncthreads();
    float r = (threadIdx.x < (blockDim.x >> 5)) ? sh[threadIdx.x] : 0.0f;
    if (w == 0) {
        #pragma unroll
        for (int o = 16; o; o >>= 1) r += __shfl_xor_sync(0xFFFFFFFFu, r, o);
        if (lane == 0) sh[0] = r;
    }
    __syncthreads();
    float out = sh[0];
    __syncthreads();
    return out;
}

// ---------------------------------------------------------------------------
// fp32 -> fp16 convert (vectorized, contiguous)
// ---------------------------------------------------------------------------
__global__ void tohalf_kernel(const float* __restrict__ s,
                              __half* __restrict__ d, size_t n4)
{
    size_t i = (size_t)blockIdx.x * blockDim.x + threadIdx.x;
    if (i >= n4) return;
    float4 v = reinterpret_cast<const float4*>(s)[i];
    __half2 h0 = __floats2half2_rn(v.x, v.y);
    __half2 h1 = __floats2half2_rn(v.z, v.w);
    uint2 o;
    o.x = *reinterpret_cast<uint32_t*>(&h0);
    o.y = *reinterpret_cast<uint32_t*>(&h1);
    reinterpret_cast<uint2*>(d)[i] = o;
}

// ---------------------------------------------------------------------------
// Pack W_out[:, 0:2048] (stride 4096) into wcomb[:, 0:2048] (stride 2112) fp16
// ---------------------------------------------------------------------------
__global__ void wout1_pack_kernel(const float* __restrict__ wout,
                                  __half* __restrict__ wcomb)
{
    int idx = blockIdx.x * 256 + threadIdx.x;   // over 2048*2048/4 float4
    int row = idx >> 9;                          // / 512
    int c4  = idx & 511;
    float4 v = *reinterpret_cast<const float4*>(wout + (size_t)row * 2 * D_DIM + c4 * 4);
    __half2 h0 = __floats2half2_rn(v.x, v.y);
    __half2 h1 = __floats2half2_rn(v.z, v.w);
    uint2 o;
    o.x = *reinterpret_cast<uint32_t*>(&h0);
    o.y = *reinterpret_cast<uint32_t*>(&h1);
    *reinterpret_cast<uint2*>(wcomb + (size_t)row * KCOMB + c4 * 4) = o;
}

// ---------------------------------------------------------------------------
// P2[s][n] = sum_k protos[s][k] * W_out[n][2048+k]  -> wcomb[n][2048+s] (fp16)
// grid = 16 blocks (n tiles of 128), 256 threads.
// ---------------------------------------------------------------------------
__global__ void __launch_bounds__(256)
p2_kernel(const float* __restrict__ protos, const float* __restrict__ wout,
          __half* __restrict__ wcomb)
{
    constexpr int BKC = 32, PAD = 4;
    __shared__ float Pt[S_PROTO][BKC + PAD];
    __shared__ float Wt[128][BKC + PAD];

    const int tid = threadIdx.x;
    const int n0 = blockIdx.x * 128;
    const int tr = tid >> 4;      // 0..15 -> s base tr*4
    const int tc = tid & 15;      // 0..15 -> n base tc*8

    float acc[4][8];
    #pragma unroll
    for (int i = 0; i < 4; i++)
        #pragma unroll
        for (int j = 0; j < 8; j++) acc[i][j] = 0.0f;

    for (int kt = 0; kt < D_DIM; kt += BKC) {
        // load protos tile: 64 x 32 = 512 float4
        #pragma unroll
        for (int i = 0; i < 2; i++) {
            int idx = tid + i * 256;
            int row = idx >> 3, c4 = idx & 7;
            float4 v = *reinterpret_cast<const float4*>(
                protos + (size_t)row * D_DIM + kt + c4 * 4);
            Pt[row][c4*4+0] = v.x; Pt[row][c4*4+1] = v.y;
            Pt[row][c4*4+2] = v.z; Pt[row][c4*4+3] = v.w;
        }
        // load W_out2 tile: 128 x 32 = 1024 float4
        #pragma unroll
        for (int i = 0; i < 4; i++) {
            int idx = tid + i * 256;
            int row = idx >> 3, c4 = idx & 7;
            float4 v = *reinterpret_cast<const float4*>(
                wout + (size_t)(n0 + row) * 2 * D_DIM + D_DIM + kt + c4 * 4);
            Wt[row][c4*4+0] = v.x; Wt[row][c4*4+1] = v.y;
            Wt[row][c4*4+2] = v.z; Wt[row][c4*4+3] = v.w;
        }
        __syncthreads();
        #pragma unroll 8
        for (int k = 0; k < BKC; k++) {
            float p[4], w[8];
            #pragma unroll
            for (int i = 0; i < 4; i++) p[i] = Pt[tr*4+i][k];
            #pragma unroll
            for (int j = 0; j < 8; j++) w[j] = Wt[tc*8+j][k];
            #pragma unroll
            for (int i = 0; i < 4; i++)
                #pragma unroll
                for (int j = 0; j < 8; j++)
                    acc[i][j] = fmaf(p[i], w[j], acc[i][j]);
        }
        __syncthreads();
    }
    #pragma unroll
    for (int i = 0; i < 4; i++)
        #pragma unroll
        for (int j = 0; j < 8; j++)
            wcomb[(size_t)(n0 + tc*8 + j) * KCOMB + D_DIM + tr*4 + i] =
                __float2half_rn(acc[i][j]);
}

// ---------------------------------------------------------------------------
// Single-pass fp16 HMMA GEMM: C[M,N] = act(A*B^T + bias) (+ residual)
// MODE bits: 1=gelu, 2=+Xres, 4=split-A (A stride strideA, A2 stride strideA2),
//   8=dual-output (blocks with blockIdx.x >= NXtiles use second set, gelued).
// BM=BN=128, BK=64, 3-stage cp.async, 256 threads, 2 CTAs/SM.
// ---------------------------------------------------------------------------
template<int MODE>
__global__ void __launch_bounds__(256, 2)
mma_gemm(const __half* __restrict__ A, const __half* __restrict__ A2,
         const __half* __restrict__ Bm,
         const float* __restrict__ bias, const float* __restrict__ Xres,
         float* __restrict__ C, int N, int K, int Ksplit,
         int strideA, int strideA2,
         const __half* __restrict__ B2,
         const float* __restrict__ bias2, float* __restrict__ C2,
         int N2, int NXtiles)
{
    constexpr int BM = 128, BK = 64, STAGES = 3;
    constexpr int TILE_B  = BM * BK * 2;
    constexpr int STAGE_B = 2 * TILE_B;

    extern __shared__ __align__(16) char smem[];
    const uint32_t sbase = smem_to_u32(smem);

    const int tid  = threadIdx.x;
    const int wid  = tid >> 5, lane = tid & 31;
    const int m0 = blockIdx.y * BM;

    int bx = blockIdx.x;
    bool second = false;
    if constexpr (MODE & 8) {
        if (bx >= NXtiles) { second = true; bx -= NXtiles; }
    }
    const __half* pB = second ? B2 : Bm;
    const float* pbias = second ? bias2 : bias;
    float* pC = second ? C2 : C;
    const int NN = second ? N2 : N;
    const int n0 = bx * BM;
    const bool do_gelu = (MODE & 1) || second;

    const int wm = (wid >> 2) * 64;
    const int wn = (wid & 3) * 32;

    float acc[4][4][4];
    #pragma unroll
    for (int i = 0; i < 4; i++)
        #pragma unroll
        for (int j = 0; j < 4; j++)
            #pragma unroll
            for (int k = 0; k < 4; k++) acc[i][j][k] = 0.0f;

    const int nk = K / BK;

    auto load_stage = [&](int s, int t) {
        const int k0 = t * BK;
        const __half* pA = A;
        int ka = k0, sA = strideA;
        if constexpr (MODE & 4) {
            if (k0 >= Ksplit) { pA = A2; ka = k0 - Ksplit; sA = strideA2; }
        }
        const uint32_t sb = sbase + s * STAGE_B;
        #pragma unroll
        for (int i = 0; i < 4; i++) {
            int idx = tid + i * 256;
            int row = idx >> 3, g = idx & 7;
            int gs  = g ^ (row & 7);
            uint32_t so = row * 128 + gs * 16;
            size_t ga = (size_t)(m0 + row) * sA + ka + g * 8;
            size_t gb = (size_t)(n0 + row) * K + k0 + g * 8;
            cpasync16(sb + so, pA + ga);
            cpasync16(sb + TILE_B + so, pB + gb);
        }
    };

    auto compute_stage = [&](int s) {
        const uint32_t sb = sbase + s * STAGE_B;
        #pragma unroll
        for (int ks = 0; ks < 4; ks++) {
            uint32_t afr[4][4], bfr[2][4];
            #pragma unroll
            for (int mf = 0; mf < 4; mf++) {
                int row = wm + mf * 16 + (lane & 15);
                int g   = ks * 2 + (lane >> 4);
                ldsm4(afr[mf], sb + row * 128 + ((g ^ (row & 7)) * 16));
            }
            #pragma unroll
            for (int nf2 = 0; nf2 < 2; nf2++) {
                int nrow = wn + nf2 * 16 + ((lane >> 4) & 1) * 8 + (lane & 7);
                int g    = ks * 2 + ((lane >> 3) & 1);
                ldsm4(bfr[nf2], sb + TILE_B + nrow * 128 + ((g ^ (nrow & 7)) * 16));
            }
            #pragma unroll
            for (int mf = 0; mf < 4; mf++)
                #pragma unroll
                for (int nf = 0; nf < 4; nf++)
                    mma_f16(acc[mf][nf], afr[mf], &bfr[nf >> 1][(nf & 1) * 2]);
        }
    };

    load_stage(0, 0); CP_COMMIT();
    load_stage(1, 1); CP_COMMIT();

    for (int t = 0; t < nk; t++) {
        CP_WAIT(STAGES - 2);
        __syncthreads();
        if (t + STAGES - 1 < nk) load_stage((t + STAGES - 1) % STAGES, t + STAGES - 1);
        CP_COMMIT();
        compute_stage(t % STAGES);
    }

    #pragma unroll
    for (int mf = 0; mf < 4; mf++)
        #pragma unroll
        for (int nf = 0; nf < 4; nf++)
            #pragma unroll
            for (int half = 0; half < 2; half++) {
                int row = m0 + wm + mf * 16 + (lane >> 2) + half * 8;
                int col = n0 + wn + nf * 8 + (lane & 3) * 2;
                float v0 = acc[mf][nf][half * 2 + 0] + pbias[col];
                float v1 = acc[mf][nf][half * 2 + 1] + pbias[col + 1];
                if (do_gelu) { v0 = gelu_exact(v0); v1 = gelu_exact(v1); }
                if constexpr (MODE & 2) {
                    float2 xr = *reinterpret_cast<const float2*>(
                        &Xres[(size_t)row * NN + col]);
                    v0 += xr.x; v1 += xr.y;
                }
                float2 o; o.x = v0; o.y = v1;
                *reinterpret_cast<float2*>(&pC[(size_t)row * NN + col]) = o;
            }
}

// ---------------------------------------------------------------------------
// Fused: row-norms of h + sim GEMM (h @ pn^T) + salience + softmax -> attn fp16
// BM=128, BN=64 (= S), BK=16, 256 threads, fp32 SIMT.
// ---------------------------------------------------------------------------
__global__ void __launch_bounds__(256)
sim_attn_kernel(const float* __restrict__ A, const float* __restrict__ Bm,
                const float* __restrict__ tw, __half* __restrict__ attn)
{
    constexpr int BM = 128, BN = 64, BK = 16, TM = 8, TN = 4, PAD = 4;
    constexpr int KV = BK / 4;
    constexpr int AS_B = 2 * BK * (BM + PAD) * 4;
    constexpr int SSQ_OFF = 33280;

    extern __shared__ __align__(16) char dsm[];
    float (*As)[BK][BM + PAD] = reinterpret_cast<float (*)[BK][BM + PAD]>(dsm);
    float (*Bs)[BK][BN + PAD] = reinterpret_cast<float (*)[BK][BN + PAD]>(dsm + AS_B);
    float* sal = reinterpret_cast<float*>(dsm);
    float* ssq_sm = reinterpret_cast<float*>(dsm + SSQ_OFF);

    const int tid = threadIdx.x;
    const int m0 = blockIdx.y * BM;
    const int tr = tid / 16;
    const int tc = tid % 16;

    const int K = D_DIM;
    float4 aReg[2]; float4 bReg;
    float acc[TM][TN];
    float ssq[2] = {0.f, 0.f};
    #pragma unroll
    for (int i = 0; i < TM; i++)
        #pragma unroll
        for (int j = 0; j < TN; j++) acc[i][j] = 0.0f;

    auto fetch = [&](int kt) {
        #pragma unroll
        for (int i = 0; i < 2; i++) {
            int idx = tid + i * 256;
            int row = idx / KV, kc = (idx % KV) * 4;
            aReg[i] = *reinterpret_cast<const float4*>(A + (size_t)(m0+row)*K + kt + kc);
            ssq[i] += aReg[i].x*aReg[i].x + aReg[i].y*aReg[i].y
                    + aReg[i].z*aReg[i].z + aReg[i].w*aReg[i].w;
        }
        {
            int row = tid / KV, kc = (tid % KV) * 4;
            bReg = *reinterpret_cast<const float4*>(Bm + (size_t)row*K + kt + kc);
        }
    };
    auto stash = [&](int buf) {
        #pragma unroll
        for (int i = 0; i < 2; i++) {
            int idx = tid + i * 256;
            int row = idx / KV, kc = (idx % KV) * 4;
            As[buf][kc+0][row] = aReg[i].x; As[buf][kc+1][row] = aReg[i].y;
            As[buf][kc+2][row] = aReg[i].z; As[buf][kc+3][row] = aReg[i].w;
        }
        {
            int row = tid / KV, kc = (tid % KV) * 4;
            Bs[buf][kc+0][row] = bReg.x; Bs[buf][kc+1][row] = bReg.y;
            Bs[buf][kc+2][row] = bReg.z; Bs[buf][kc+3][row] = bReg.w;
        }
    };

    fetch(0); stash(0);
    __syncthreads();

    const int nk = K / BK;
    for (int t = 0; t < nk; t++) {
        const int cur = t & 1;
        if (t + 1 < nk) fetch((t + 1) * BK);
        #pragma unroll
        for (int k = 0; k < BK; k++) {
            float a[TM], b[TN];
            #pragma unroll
            for (int i = 0; i < TM; i += 4) {
                float4 v = *reinterpret_cast<const float4*>(&As[cur][k][tr*TM + i]);
                a[i]=v.x; a[i+1]=v.y; a[i+2]=v.z; a[i+3]=v.w;
            }
            #pragma unroll
            for (int j = 0; j < TN; j += 4) {
                float4 v = *reinterpret_cast<const float4*>(&Bs[cur][k][tc*TN + j]);
                b[j]=v.x; b[j+1]=v.y; b[j+2]=v.z; b[j+3]=v.w;
            }
            #pragma unroll
            for (int i = 0; i < TM; i++)
                #pragma unroll
                for (int j = 0; j < TN; j++)
                    acc[i][j] = fmaf(a[i], b[j], acc[i][j]);
        }
        if (t + 1 < nk) stash(cur ^ 1);
        __syncthreads();
    }

    #pragma unroll
    for (int i = 0; i < 2; i++) {
        ssq[i] += __shfl_xor_sync(0xFFFFFFFFu, ssq[i], 1);
        ssq[i] += __shfl_xor_sync(0xFFFFFFFFu, ssq[i], 2);
    }
    if ((tid & 3) == 0) {
        ssq_sm[tid / 4]      = ssq[0];
        ssq_sm[64 + tid / 4] = ssq[1];
    }
    __syncthreads();

    #pragma unroll
    for (int i = 0; i < TM; i++) {
        int row = tr * TM + i;
        float invn = 1.0f / fmaxf(sqrtf(ssq_sm[row]), 1e-12f);
        float twv = tw[(size_t)(m0 + row) * 4 + (tc >> 2)];
        #pragma unroll
        for (int j = 0; j < TN; j++) {
            int col = tc * TN + j;
            float v = g_wsimc[col] * twv * (acc[i][j] * invn) + g_base[col];
            sal[row * 65 + col] = fminf(fmaxf(v, 0.0f), 1.0f);
        }
    }
    __syncthreads();

    {
        int row = tid >> 1, half = tid & 1;
        const float* srow = &sal[row * 65 + half * 32];
        float m = -1e30f;
        #pragma unroll
        for (int c = 0; c < 32; c++) m = fmaxf(m, srow[c]);
        m = fmaxf(m, __shfl_xor_sync(0xFFFFFFFFu, m, 1));
        const float invT = 1.0f / 0.07f;
        float e[32], s = 0.0f;
        #pragma unroll
        for (int c = 0; c < 32; c++) { e[c] = expf((srow[c] - m) * invT); s += e[c]; }
        s += __shfl_xor_sync(0xFFFFFFFFu, s, 1);
        float inv = 1.0f / s;
        __half* dst = &attn[(size_t)(m0 + row) * S_PROTO + half * 32];
        #pragma unroll
        for (int c = 0; c < 32; c += 2) {
            __half2 o = __floats2half2_rn(e[c] * inv, e[c+1] * inv);
            *reinterpret_cast<__half2*>(dst + c) = o;
        }
    }
}

// ---------------------------------------------------------------------------
// Prototype prep
// ---------------------------------------------------------------------------
__global__ void proto_prep(const float* __restrict__ protos,
                           const float* __restrict__ conf,
                           const float* __restrict__ age,
                           const float* __restrict__ ev)
{
    const int s = blockIdx.x;
    float ss = 0.0f;
    for (int k = threadIdx.x; k < D_DIM; k += 256) {
        float v = protos[(size_t)s * D_DIM + k];
        ss += v * v;
    }
    float tot = block_reduce_sum(ss);
    float scale = 1.0f / fmaxf(sqrtf(tot), 1e-12f);
    for (int k = threadIdx.x; k < D_DIM; k += 256)
        g_pn[(size_t)s * D_DIM + k] = protos[(size_t)s * D_DIM + k] * scale;

    if (threadIdx.x == 0) {
        float evmax = 0.0f;
        for (int i = 0; i < S_PROTO; i++) evmax = fmaxf(evmax, ev[i]);
        float freq = logf(ev[s] + 1.0f) / (logf(evmax + 2.0f) + 1e-8f);
        float rec  = expf(-age[s] * (1.0f / 200.0f));
        g_base[s]  = 0.2f * rec + 0.15f * freq + 0.1f * conf[s] + 0.1f * 0.9f;
        g_wsimc[s] = 0.45f * conf[s];
    }
}

// ---------------------------------------------------------------------------
// Type weights softmax (4 logits). 1 warp per row.
// ---------------------------------------------------------------------------
__global__ void type_weights_kernel(const float* __restrict__ r,
                                    const float* __restrict__ Wr2,
                                    const float* __restrict__ br2,
                                    float* __restrict__ tw)
{
    const int warp = threadIdx.x >> 5, lane = threadIdx.x & 31;
    const int b = blockIdx.x * 8 + warp;
    const float4* rp = reinterpret_cast<const float4*>(r + (size_t)b * D_HALF);
    float acc[4] = {0.f, 0.f, 0.f, 0.f};
    for (int i = lane; i < D_HALF / 4; i += 32) {
        float4 rv = rp[i];
        #pragma unroll
        for (int t = 0; t < 4; t++) {
            float4 wv = reinterpret_cast<const float4*>(Wr2 + (size_t)t * D_HALF)[i];
            acc[t] += rv.x*wv.x + rv.y*wv.y + rv.z*wv.z + rv.w*wv.w;
        }
    }
    #pragma unroll
    for (int t = 0; t < 4; t++)
        #pragma unroll
        for (int o = 16; o; o >>= 1)
            acc[t] += __shfl_xor_sync(0xFFFFFFFFu, acc[t], o);
    if (lane == 0) {
        float z[4], m = -1e30f;
        #pragma unroll
        for (int t = 0; t < 4; t++) { z[t] = acc[t] + br2[t]; m = fmaxf(m, z[t]); }
        float s = 0.0f;
        #pragma unroll
        for (int t = 0; t < 4; t++) { z[t] = expf(z[t] - m); s += z[t]; }
        float inv = 1.0f / s;
        #pragma unroll
        for (int t = 0; t < 4; t++) tw[(size_t)b * 4 + t] = z[t] * inv;
    }
}

// ---------------------------------------------------------------------------
// In-place LayerNorm over D
// ---------------------------------------------------------------------------
__global__ void layernorm_inplace(float* __restrict__ y,
                                  const float* __restrict__ w,
                                  const float* __restrict__ bb)
{
    const size_t base = (size_t)blockIdx.x * D_DIM;
    float4* yp = reinterpret_cast<float4*>(y + base);
    float4 v[2];
    float sum = 0.0f;
    #pragma unroll
    for (int i = 0; i < 2; i++) {
        v[i] = yp[threadIdx.x + 256 * i];
        sum += v[i].x + v[i].y + v[i].z + v[i].w;
    }
    float mu = block_reduce_sum(sum) * (1.0f / D_DIM);
    float sq = 0.0f;
    #pragma unroll
    for (int i = 0; i < 2; i++) {
        float dx = v[i].x - mu, dy = v[i].y - mu, dz = v[i].z - mu, dw = v[i].w - mu;
        sq += dx*dx + dy*dy + dz*dz + dw*dw;
    }
    float var = block_reduce_sum(sq) * (1.0f / D_DIM);
    float rstd = rsqrtf(var + 1e-5f);
    #pragma unroll
    for (int i = 0; i < 2; i++) {
        int col = (threadIdx.x + 256 * i) * 4;
        float4 wv = *reinterpret_cast<const float4*>(&w[col]);
        float4 bv = *reinterpret_cast<const float4*>(&bb[col]);
        float4 o;
        o.x = wv.x * (v[i].x - mu) * rstd + bv.x;
        o.y = wv.y * (v[i].y - mu) * rstd + bv.y;
        o.z = wv.z * (v[i].z - mu) * rstd + bv.z;
        o.w = wv.w * (v[i].w - mu) * rstd + bv.w;
        yp[threadIdx.x + 256 * i] = o;
    }
}

// ---------------------------------------------------------------------------
// Launch
// ---------------------------------------------------------------------------
extern "C" void kernel_launch(void* const* d_in, const int* in_sizes, int n_in,
                              void* d_out, int out_size)
{
    const float* x      = (const float*)d_in[0];
    const float* protos = (const float*)d_in[1];
    const float* conf   = (const float*)d_in[2];
    const float* age    = (const float*)d_in[3];
    const float* ev     = (const float*)d_in[4];
    const float* W_in   = (const float*)d_in[5];
    const float* b_in   = (const float*)d_in[6];
    const float* Wr1    = (const float*)d_in[7];
    const float* br1    = (const float*)d_in[8];
    const float* Wr2    = (const float*)d_in[9];
    const float* br2    = (const float*)d_in[10];
    const float* W_out  = (const float*)d_in[11];
    const float* b_out  = (const float*)d_in[12];
    const float* ln_w   = (const float*)d_in[13];
    const float* ln_b   = (const float*)d_in[14];
    float* out = (float*)d_out;

    __half *xh, *winh, *wr1h, *wcomb, *attnh;
    float *h, *r, *tw, *pn;
    cudaGetSymbolAddress((void**)&xh,    g_x_h);
    cudaGetSymbolAddress((void**)&winh,  g_Win_h);
    cudaGetSymbolAddress((void**)&wr1h,  g_Wr1_h);
    cudaGetSymbolAddress((void**)&wcomb, g_wcomb);
    cudaGetSymbolAddress((void**)&attnh, g_attn_h);
    cudaGetSymbolAddress((void**)&h,    g_h);
    cudaGetSymbolAddress((void**)&r,    g_r);
    cudaGetSymbolAddress((void**)&tw,   g_tw);
    cudaGetSymbolAddress((void**)&pn,   g_pn);

    constexpr int SMEM_SZ = 3 * 2 * 128 * 64 * 2;   // 98304 bytes
    cudaFuncSetAttribute(mma_gemm<8>, cudaFuncAttributeMaxDynamicSharedMemorySize, SMEM_SZ);
    cudaFuncSetAttribute(mma_gemm<7>, cudaFuncAttributeMaxDynamicSharedMemorySize, SMEM_SZ);

    const int B = B_ROWS;

    // fp16 conversions + combined W_out build
    {
        size_t n4;
        n4 = (size_t)B * D_DIM / 4;
        tohalf_kernel<<<(unsigned)((n4 + 255) / 256), 256>>>(x, xh, n4);
        n4 = (size_t)D_DIM * D_DIM / 4;
        tohalf_kernel<<<(unsigned)((n4 + 255) / 256), 256>>>(W_in, winh, n4);
        n4 = (size_t)D_HALF * D_DIM / 4;
        tohalf_kernel<<<(unsigned)((n4 + 255) / 256), 256>>>(Wr1, wr1h, n4);
        wout1_pack_kernel<<<(D_DIM * D_DIM / 4) / 256, 256>>>(W_out, wcomb);
        p2_kernel<<<D_DIM / 128, 256>>>(protos, W_out, wcomb);
    }

    proto_prep<<<S_PROTO, 256>>>(protos, conf, age, ev);

    // G1+G2 fused: h = x@W_in^T + b_in ; r = gelu(x@Wr1^T + br1)
    mma_gemm<8><<<dim3(D_DIM / 128 + D_HALF / 128, B / 128), 256, SMEM_SZ>>>(
        xh, nullptr, winh, b_in, nullptr, h,
        D_DIM, D_DIM, 0, D_DIM, 0,
        wr1h, br1, r, D_HALF, D_DIM / 128);

    type_weights_kernel<<<B / 8, 256>>>(r, Wr2, br2, tw);

    // fused rownorm + sim + salience + softmax -> attn (fp16)
    sim_attn_kernel<<<dim3(1, B / 128), 256, 33792>>>(h, pn, tw, attnh);

    // G3: out = gelu([x | attn] @ [W_out1 | P2]^T + b_out) + x    (K = 2112)
    mma_gemm<7><<<dim3(D_DIM / 128, B / 128), 256, SMEM_SZ>>>(
        xh, attnh, wcomb, b_out, x, out,
        D_DIM, KCOMB, D_DIM, D_DIM, S_PROTO,
        nullptr, nullptr, nullptr, 0, 0x7FFFFFFF);

    layernorm_inplace<<<B, 256>>>(out, ln_w, ln_b);
}

// round 7
// speedup vs baseline: 1.4336x; 1.4336x over previous
#include <cuda_runtime.h>
#include <cuda_fp16.h>
#include <math.h>
#include <stdint.h>

#define B_ROWS 16384
#define D_DIM  2048
#define D_HALF 1024
#define S_PROTO 64
#define KCOMB  (D_DIM + S_PROTO)   // 2112

// ---------------------------------------------------------------------------
// Scratch (device globals; allocation-free per harness rules)
// ---------------------------------------------------------------------------
__device__ __half g_x_h[(size_t)B_ROWS * D_DIM];
__device__ __half g_Win_h[(size_t)D_DIM * D_DIM];
__device__ __half g_Wr1_h[(size_t)D_HALF * D_DIM];
__device__ __half g_wcomb[(size_t)D_DIM * KCOMB];      // [W_out1 | P2^T] fp16
__device__ __half g_attn_h[(size_t)B_ROWS * S_PROTO];
__device__ float g_p2part[4 * S_PROTO * D_DIM];        // k-split partials
__device__ float g_h[(size_t)B_ROWS * D_DIM];
__device__ float g_r[(size_t)B_ROWS * D_HALF];
__device__ float g_tw[(size_t)B_ROWS * 4];
__device__ float g_pn[(size_t)S_PROTO * D_DIM];
__device__ float g_base[S_PROTO];
__device__ float g_wsimc[S_PROTO];

// ---------------------------------------------------------------------------
// PTX helpers (baseline ISA: mma.sync / ldmatrix / cp.async)
// ---------------------------------------------------------------------------
__device__ __forceinline__ uint32_t smem_to_u32(const void* p) {
    uint32_t a;
    asm("{ .reg .u64 t; cvta.to.shared.u64 t, %1; cvt.u32.u64 %0, t; }"
        : "=r"(a) : "l"(p));
    return a;
}

__device__ __forceinline__ void cpasync16(uint32_t saddr, const void* g) {
    asm volatile("cp.async.cg.shared.global [%0], [%1], 16;"
                 :: "r"(saddr), "l"(g));
}
#define CP_COMMIT() asm volatile("cp.async.commit_group;" ::: "memory")
#define CP_WAIT(n)  asm volatile("cp.async.wait_group %0;" :: "n"(n) : "memory")

__device__ __forceinline__ void ldsm4(uint32_t* r, uint32_t addr) {
    asm volatile("ldmatrix.sync.aligned.m8n8.x4.shared.b16 {%0,%1,%2,%3}, [%4];"
                 : "=r"(r[0]), "=r"(r[1]), "=r"(r[2]), "=r"(r[3]) : "r"(addr));
}

__device__ __forceinline__ void mma_f16(float* d, const uint32_t* a, const uint32_t* b) {
    asm volatile(
        "mma.sync.aligned.m16n8k16.row.col.f32.f16.f16.f32 "
        "{%0,%1,%2,%3}, {%4,%5,%6,%7}, {%8,%9}, {%0,%1,%2,%3};"
        : "+f"(d[0]), "+f"(d[1]), "+f"(d[2]), "+f"(d[3])
        : "r"(a[0]), "r"(a[1]), "r"(a[2]), "r"(a[3]), "r"(b[0]), "r"(b[1]));
}

// ---------------------------------------------------------------------------
// Misc helpers
// ---------------------------------------------------------------------------
__device__ __forceinline__ float gelu_exact(float v) {
    return 0.5f * v * (1.0f + erff(v * 0.70710678118654752440f));
}

__device__ __forceinline__ float block_reduce_sum(float v) {
    __shared__ float sh[32];
    int lane = threadIdx.x & 31, w = threadIdx.x >> 5;
    #pragma unroll
    for (int o = 16; o; o >>= 1) v += __shfl_xor_sync(0xFFFFFFFFu, v, o);
    if (lane == 0) sh[w] = v;
    __syncthreads();
    float r = (threadIdx.x < (blockDim.x >> 5)) ? sh[threadIdx.x] : 0.0f;
    if (w == 0) {
        #pragma unroll
        for (int o = 16; o; o >>= 1) r += __shfl_xor_sync(0xFFFFFFFFu, r, o);
        if (lane == 0) sh[0] = r;
    }
    __syncthreads();
    float out = sh[0];
    __syncthreads();
    return out;
}

// ---------------------------------------------------------------------------
// fp32 -> fp16 convert (vectorized, contiguous)
// ---------------------------------------------------------------------------
__global__ void tohalf_kernel(const float* __restrict__ s,
                              __half* __restrict__ d, size_t n4)
{
    size_t i = (size_t)blockIdx.x * blockDim.x + threadIdx.x;
    if (i >= n4) return;
    float4 v = reinterpret_cast<const float4*>(s)[i];
    __half2 h0 = __floats2half2_rn(v.x, v.y);
    __half2 h1 = __floats2half2_rn(v.z, v.w);
    uint2 o;
    o.x = *reinterpret_cast<uint32_t*>(&h0);
    o.y = *reinterpret_cast<uint32_t*>(&h1);
    reinterpret_cast<uint2*>(d)[i] = o;
}

// ---------------------------------------------------------------------------
// Pack W_out[:, 0:2048] (stride 4096) into wcomb[:, 0:2048] (stride 2112) fp16
// ---------------------------------------------------------------------------
__global__ void wout1_pack_kernel(const float* __restrict__ wout,
                                  __half* __restrict__ wcomb)
{
    int idx = blockIdx.x * 256 + threadIdx.x;   // over 2048*2048/4 float4
    int row = idx >> 9;
    int c4  = idx & 511;
    float4 v = *reinterpret_cast<const float4*>(wout + (size_t)row * 2 * D_DIM + c4 * 4);
    __half2 h0 = __floats2half2_rn(v.x, v.y);
    __half2 h1 = __floats2half2_rn(v.z, v.w);
    uint2 o;
    o.x = *reinterpret_cast<uint32_t*>(&h0);
    o.y = *reinterpret_cast<uint32_t*>(&h1);
    *reinterpret_cast<uint2*>(wcomb + (size_t)row * KCOMB + c4 * 4) = o;
}

// ---------------------------------------------------------------------------
// P2 partials (k-split, conflict-free transposed tiles):
//   part[ks][s][n] = sum_{k in slice ks} protos[s][k] * W_out[n][2048+k]
// grid = (16 n-tiles of 128, 4 k-slices of 512), 256 threads.
// ---------------------------------------------------------------------------
__global__ void __launch_bounds__(256)
p2_kernel(const float* __restrict__ protos, const float* __restrict__ wout,
          float* __restrict__ part)
{
    constexpr int BKC = 32;
    __shared__ float Pt[BKC][68];    // [k][s], stride 68 (f4-aligned, depadded)
    __shared__ float Wt[BKC][132];   // [k][n], stride 132

    const int tid = threadIdx.x;
    const int n0 = blockIdx.x * 128;
    const int kb = blockIdx.y * 512;
    const int tr = tid >> 4;      // 0..15 -> s base tr*4
    const int tc = tid & 15;      // 0..15 -> n base tc*8

    float acc[4][8];
    #pragma unroll
    for (int i = 0; i < 4; i++)
        #pragma unroll
        for (int j = 0; j < 8; j++) acc[i][j] = 0.0f;

    for (int kt = 0; kt < 512; kt += BKC) {
        // protos tile: 64 s x 32 k (coalesced reads, transposed store)
        #pragma unroll
        for (int i = 0; i < 2; i++) {
            int idx = tid + i * 256;
            int s = idx >> 3, kq = (idx & 7) * 4;
            float4 v = *reinterpret_cast<const float4*>(
                protos + (size_t)s * D_DIM + kb + kt + kq);
            Pt[kq+0][s] = v.x; Pt[kq+1][s] = v.y;
            Pt[kq+2][s] = v.z; Pt[kq+3][s] = v.w;
        }
        // W_out2 tile: 128 n x 32 k
        #pragma unroll
        for (int i = 0; i < 4; i++) {
            int idx = tid + i * 256;
            int n = idx >> 3, kq = (idx & 7) * 4;
            float4 v = *reinterpret_cast<const float4*>(
                wout + (size_t)(n0 + n) * 2 * D_DIM + D_DIM + kb + kt + kq);
            Wt[kq+0][n] = v.x; Wt[kq+1][n] = v.y;
            Wt[kq+2][n] = v.z; Wt[kq+3][n] = v.w;
        }
        __syncthreads();
        #pragma unroll 8
        for (int k = 0; k < BKC; k++) {
            float4 p  = *reinterpret_cast<const float4*>(&Pt[k][tr * 4]);
            float4 wa = *reinterpret_cast<const float4*>(&Wt[k][tc * 8]);
            float4 wb = *reinterpret_cast<const float4*>(&Wt[k][tc * 8 + 4]);
            float pv[4] = {p.x, p.y, p.z, p.w};
            float wv[8] = {wa.x, wa.y, wa.z, wa.w, wb.x, wb.y, wb.z, wb.w};
            #pragma unroll
            for (int i = 0; i < 4; i++)
                #pragma unroll
                for (int j = 0; j < 8; j++)
                    acc[i][j] = fmaf(pv[i], wv[j], acc[i][j]);
        }
        __syncthreads();
    }

    float* dst = part + (size_t)blockIdx.y * S_PROTO * D_DIM;
    #pragma unroll
    for (int i = 0; i < 4; i++)
        #pragma unroll
        for (int j = 0; j < 8; j++)
            dst[(size_t)(tr * 4 + i) * D_DIM + n0 + tc * 8 + j] = acc[i][j];
}

// ---------------------------------------------------------------------------
// Reduce 4 partials -> wcomb[n][2048+s] fp16. Deterministic fixed-order sum.
// grid = 512 blocks x 256 threads covers 64*2048.
// ---------------------------------------------------------------------------
__global__ void p2_reduce_kernel(const float* __restrict__ part,
                                 __half* __restrict__ wcomb)
{
    int idx = blockIdx.x * 256 + threadIdx.x;   // 0..131071
    int s = idx >> 11;          // 0..63
    int n = idx & 2047;         // coalesced over part rows
    size_t o = (size_t)s * D_DIM + n;
    float v = part[o] + part[o + S_PROTO * D_DIM]
            + part[o + 2 * S_PROTO * D_DIM] + part[o + 3 * S_PROTO * D_DIM];
    wcomb[(size_t)n * KCOMB + D_DIM + s] = __float2half_rn(v);
}

// ---------------------------------------------------------------------------
// Single-pass fp16 HMMA GEMM: C[M,N] = act(A*B^T + bias) (+ residual)
// MODE bits: 1=gelu, 2=+Xres, 4=split-A (A stride strideA, A2 stride strideA2),
//   8=dual-output (blocks with blockIdx.x >= NXtiles use second set, gelued).
// BM=BN=128, BK=64, 3-stage cp.async, 256 threads, 2 CTAs/SM.
// ---------------------------------------------------------------------------
template<int MODE>
__global__ void __launch_bounds__(256, 2)
mma_gemm(const __half* __restrict__ A, const __half* __restrict__ A2,
         const __half* __restrict__ Bm,
         const float* __restrict__ bias, const float* __restrict__ Xres,
         float* __restrict__ C, int N, int K, int Ksplit,
         int strideA, int strideA2,
         const __half* __restrict__ B2,
         const float* __restrict__ bias2, float* __restrict__ C2,
         int N2, int NXtiles)
{
    constexpr int BM = 128, BK = 64, STAGES = 3;
    constexpr int TILE_B  = BM * BK * 2;
    constexpr int STAGE_B = 2 * TILE_B;

    extern __shared__ __align__(16) char smem[];
    const uint32_t sbase = smem_to_u32(smem);

    const int tid  = threadIdx.x;
    const int wid  = tid >> 5, lane = tid & 31;
    const int m0 = blockIdx.y * BM;

    int bx = blockIdx.x;
    bool second = false;
    if constexpr (MODE & 8) {
        if (bx >= NXtiles) { second = true; bx -= NXtiles; }
    }
    const __half* pB = second ? B2 : Bm;
    const float* pbias = second ? bias2 : bias;
    float* pC = second ? C2 : C;
    const int NN = second ? N2 : N;
    const int n0 = bx * BM;
    const bool do_gelu = (MODE & 1) || second;

    const int wm = (wid >> 2) * 64;
    const int wn = (wid & 3) * 32;

    float acc[4][4][4];
    #pragma unroll
    for (int i = 0; i < 4; i++)
        #pragma unroll
        for (int j = 0; j < 4; j++)
            #pragma unroll
            for (int k = 0; k < 4; k++) acc[i][j][k] = 0.0f;

    const int nk = K / BK;

    auto load_stage = [&](int s, int t) {
        const int k0 = t * BK;
        const __half* pA = A;
        int ka = k0, sA = strideA;
        if constexpr (MODE & 4) {
            if (k0 >= Ksplit) { pA = A2; ka = k0 - Ksplit; sA = strideA2; }
        }
        const uint32_t sb = sbase + s * STAGE_B;
        #pragma unroll
        for (int i = 0; i < 4; i++) {
            int idx = tid + i * 256;
            int row = idx >> 3, g = idx & 7;
            int gs  = g ^ (row & 7);
            uint32_t so = row * 128 + gs * 16;
            size_t ga = (size_t)(m0 + row) * sA + ka + g * 8;
            size_t gb = (size_t)(n0 + row) * K + k0 + g * 8;
            cpasync16(sb + so, pA + ga);
            cpasync16(sb + TILE_B + so, pB + gb);
        }
    };

    auto compute_stage = [&](int s) {
        const uint32_t sb = sbase + s * STAGE_B;
        #pragma unroll
        for (int ks = 0; ks < 4; ks++) {
            uint32_t afr[4][4], bfr[2][4];
            #pragma unroll
            for (int mf = 0; mf < 4; mf++) {
                int row = wm + mf * 16 + (lane & 15);
                int g   = ks * 2 + (lane >> 4);
                ldsm4(afr[mf], sb + row * 128 + ((g ^ (row & 7)) * 16));
            }
            #pragma unroll
            for (int nf2 = 0; nf2 < 2; nf2++) {
                int nrow = wn + nf2 * 16 + ((lane >> 4) & 1) * 8 + (lane & 7);
                int g    = ks * 2 + ((lane >> 3) & 1);
                ldsm4(bfr[nf2], sb + TILE_B + nrow * 128 + ((g ^ (nrow & 7)) * 16));
            }
            #pragma unroll
            for (int mf = 0; mf < 4; mf++)
                #pragma unroll
                for (int nf = 0; nf < 4; nf++)
                    mma_f16(acc[mf][nf], afr[mf], &bfr[nf >> 1][(nf & 1) * 2]);
        }
    };

    load_stage(0, 0); CP_COMMIT();
    load_stage(1, 1); CP_COMMIT();

    for (int t = 0; t < nk; t++) {
        CP_WAIT(STAGES - 2);
        __syncthreads();
        if (t + STAGES - 1 < nk) load_stage((t + STAGES - 1) % STAGES, t + STAGES - 1);
        CP_COMMIT();
        compute_stage(t % STAGES);
    }

    #pragma unroll
    for (int mf = 0; mf < 4; mf++)
        #pragma unroll
        for (int nf = 0; nf < 4; nf++)
            #pragma unroll
            for (int half = 0; half < 2; half++) {
                int row = m0 + wm + mf * 16 + (lane >> 2) + half * 8;
                int col = n0 + wn + nf * 8 + (lane & 3) * 2;
                float v0 = acc[mf][nf][half * 2 + 0] + pbias[col];
                float v1 = acc[mf][nf][half * 2 + 1] + pbias[col + 1];
                if (do_gelu) { v0 = gelu_exact(v0); v1 = gelu_exact(v1); }
                if constexpr (MODE & 2) {
                    float2 xr = *reinterpret_cast<const float2*>(
                        &Xres[(size_t)row * NN + col]);
                    v0 += xr.x; v1 += xr.y;
                }
                float2 o; o.x = v0; o.y = v1;
                *reinterpret_cast<float2*>(&pC[(size_t)row * NN + col]) = o;
            }
}

// ---------------------------------------------------------------------------
// Fused: row-norms of h + sim GEMM (h @ pn^T) + salience + softmax -> attn fp16
// BM=128, BN=64 (= S), BK=16, 256 threads, fp32 SIMT.
// ---------------------------------------------------------------------------
__global__ void __launch_bounds__(256)
sim_attn_kernel(const float* __restrict__ A, const float* __restrict__ Bm,
                const float* __restrict__ tw, __half* __restrict__ attn)
{
    constexpr int BM = 128, BN = 64, BK = 16, TM = 8, TN = 4, PAD = 4;
    constexpr int KV = BK / 4;
    constexpr int AS_B = 2 * BK * (BM + PAD) * 4;
    constexpr int SSQ_OFF = 33280;

    extern __shared__ __align__(16) char dsm[];
    float (*As)[BK][BM + PAD] = reinterpret_cast<float (*)[BK][BM + PAD]>(dsm);
    float (*Bs)[BK][BN + PAD] = reinterpret_cast<float (*)[BK][BN + PAD]>(dsm + AS_B);
    float* sal = reinterpret_cast<float*>(dsm);
    float* ssq_sm = reinterpret_cast<float*>(dsm + SSQ_OFF);

    const int tid = threadIdx.x;
    const int m0 = blockIdx.y * BM;
    const int tr = tid / 16;
    const int tc = tid % 16;

    const int K = D_DIM;
    float4 aReg[2]; float4 bReg;
    float acc[TM][TN];
    float ssq[2] = {0.f, 0.f};
    #pragma unroll
    for (int i = 0; i < TM; i++)
        #pragma unroll
        for (int j = 0; j < TN; j++) acc[i][j] = 0.0f;

    auto fetch = [&](int kt) {
        #pragma unroll
        for (int i = 0; i < 2; i++) {
            int idx = tid + i * 256;
            int row = idx / KV, kc = (idx % KV) * 4;
            aReg[i] = *reinterpret_cast<const float4*>(A + (size_t)(m0+row)*K + kt + kc);
            ssq[i] += aReg[i].x*aReg[i].x + aReg[i].y*aReg[i].y
                    + aReg[i].z*aReg[i].z + aReg[i].w*aReg[i].w;
        }
        {
            int row = tid / KV, kc = (tid % KV) * 4;
            bReg = *reinterpret_cast<const float4*>(Bm + (size_t)row*K + kt + kc);
        }
    };
    auto stash = [&](int buf) {
        #pragma unroll
        for (int i = 0; i < 2; i++) {
            int idx = tid + i * 256;
            int row = idx / KV, kc = (idx % KV) * 4;
            As[buf][kc+0][row] = aReg[i].x; As[buf][kc+1][row] = aReg[i].y;
            As[buf][kc+2][row] = aReg[i].z; As[buf][kc+3][row] = aReg[i].w;
        }
        {
            int row = tid / KV, kc = (tid % KV) * 4;
            Bs[buf][kc+0][row] = bReg.x; Bs[buf][kc+1][row] = bReg.y;
            Bs[buf][kc+2][row] = bReg.z; Bs[buf][kc+3][row] = bReg.w;
        }
    };

    fetch(0); stash(0);
    __syncthreads();

    const int nk = K / BK;
    for (int t = 0; t < nk; t++) {
        const int cur = t & 1;
        if (t + 1 < nk) fetch((t + 1) * BK);
        #pragma unroll
        for (int k = 0; k < BK; k++) {
            float a[TM], b[TN];
            #pragma unroll
            for (int i = 0; i < TM; i += 4) {
                float4 v = *reinterpret_cast<const float4*>(&As[cur][k][tr*TM + i]);
                a[i]=v.x; a[i+1]=v.y; a[i+2]=v.z; a[i+3]=v.w;
            }
            #pragma unroll
            for (int j = 0; j < TN; j += 4) {
                float4 v = *reinterpret_cast<const float4*>(&Bs[cur][k][tc*TN + j]);
                b[j]=v.x; b[j+1]=v.y; b[j+2]=v.z; b[j+3]=v.w;
            }
            #pragma unroll
            for (int i = 0; i < TM; i++)
                #pragma unroll
                for (int j = 0; j < TN; j++)
                    acc[i][j] = fmaf(a[i], b[j], acc[i][j]);
        }
        if (t + 1 < nk) stash(cur ^ 1);
        __syncthreads();
    }

    #pragma unroll
    for (int i = 0; i < 2; i++) {
        ssq[i] += __shfl_xor_sync(0xFFFFFFFFu, ssq[i], 1);
        ssq[i] += __shfl_xor_sync(0xFFFFFFFFu, ssq[i], 2);
    }
    if ((tid & 3) == 0) {
        ssq_sm[tid / 4]      = ssq[0];
        ssq_sm[64 + tid / 4] = ssq[1];
    }
    __syncthreads();

    #pragma unroll
    for (int i = 0; i < TM; i++) {
        int row = tr * TM + i;
        float invn = 1.0f / fmaxf(sqrtf(ssq_sm[row]), 1e-12f);
        float twv = tw[(size_t)(m0 + row) * 4 + (tc >> 2)];
        #pragma unroll
        for (int j = 0; j < TN; j++) {
            int col = tc * TN + j;
            float v = g_wsimc[col] * twv * (acc[i][j] * invn) + g_base[col];
            sal[row * 65 + col] = fminf(fmaxf(v, 0.0f), 1.0f);
        }
    }
    __syncthreads();

    {
        int row = tid >> 1, half = tid & 1;
        const float* srow = &sal[row * 65 + half * 32];
        float m = -1e30f;
        #pragma unroll
        for (int c = 0; c < 32; c++) m = fmaxf(m, srow[c]);
        m = fmaxf(m, __shfl_xor_sync(0xFFFFFFFFu, m, 1));
        const float invT = 1.0f / 0.07f;
        float e[32], s = 0.0f;
        #pragma unroll
        for (int c = 0; c < 32; c++) { e[c] = expf((srow[c] - m) * invT); s += e[c]; }
        s += __shfl_xor_sync(0xFFFFFFFFu, s, 1);
        float inv = 1.0f / s;
        __half* dst = &attn[(size_t)(m0 + row) * S_PROTO + half * 32];
        #pragma unroll
        for (int c = 0; c < 32; c += 2) {
            __half2 o = __floats2half2_rn(e[c] * inv, e[c+1] * inv);
            *reinterpret_cast<__half2*>(dst + c) = o;
        }
    }
}

// ---------------------------------------------------------------------------
// Prototype prep
// ---------------------------------------------------------------------------
__global__ void proto_prep(const float* __restrict__ protos,
                           const float* __restrict__ conf,
                           const float* __restrict__ age,
                           const float* __restrict__ ev)
{
    const int s = blockIdx.x;
    float ss = 0.0f;
    for (int k = threadIdx.x; k < D_DIM; k += 256) {
        float v = protos[(size_t)s * D_DIM + k];
        ss += v * v;
    }
    float tot = block_reduce_sum(ss);
    float scale = 1.0f / fmaxf(sqrtf(tot), 1e-12f);
    for (int k = threadIdx.x; k < D_DIM; k += 256)
        g_pn[(size_t)s * D_DIM + k] = protos[(size_t)s * D_DIM + k] * scale;

    if (threadIdx.x == 0) {
        float evmax = 0.0f;
        for (int i = 0; i < S_PROTO; i++) evmax = fmaxf(evmax, ev[i]);
        float freq = logf(ev[s] + 1.0f) / (logf(evmax + 2.0f) + 1e-8f);
        float rec  = expf(-age[s] * (1.0f / 200.0f));
        g_base[s]  = 0.2f * rec + 0.15f * freq + 0.1f * conf[s] + 0.1f * 0.9f;
        g_wsimc[s] = 0.45f * conf[s];
    }
}

// ---------------------------------------------------------------------------
// Type weights softmax (4 logits). 1 warp per row.
// ---------------------------------------------------------------------------
__global__ void type_weights_kernel(const float* __restrict__ r,
                                    const float* __restrict__ Wr2,
                                    const float* __restrict__ br2,
                                    float* __restrict__ tw)
{
    const int warp = threadIdx.x >> 5, lane = threadIdx.x & 31;
    const int b = blockIdx.x * 8 + warp;
    const float4* rp = reinterpret_cast<const float4*>(r + (size_t)b * D_HALF);
    float acc[4] = {0.f, 0.f, 0.f, 0.f};
    for (int i = lane; i < D_HALF / 4; i += 32) {
        float4 rv = rp[i];
        #pragma unroll
        for (int t = 0; t < 4; t++) {
            float4 wv = reinterpret_cast<const float4*>(Wr2 + (size_t)t * D_HALF)[i];
            acc[t] += rv.x*wv.x + rv.y*wv.y + rv.z*wv.z + rv.w*wv.w;
        }
    }
    #pragma unroll
    for (int t = 0; t < 4; t++)
        #pragma unroll
        for (int o = 16; o; o >>= 1)
            acc[t] += __shfl_xor_sync(0xFFFFFFFFu, acc[t], o);
    if (lane == 0) {
        float z[4], m = -1e30f;
        #pragma unroll
        for (int t = 0; t < 4; t++) { z[t] = acc[t] + br2[t]; m = fmaxf(m, z[t]); }
        float s = 0.0f;
        #pragma unroll
        for (int t = 0; t < 4; t++) { z[t] = expf(z[t] - m); s += z[t]; }
        float inv = 1.0f / s;
        #pragma unroll
        for (int t = 0; t < 4; t++) tw[(size_t)b * 4 + t] = z[t] * inv;
    }
}

// ---------------------------------------------------------------------------
// In-place LayerNorm over D
// ---------------------------------------------------------------------------
__global__ void layernorm_inplace(float* __restrict__ y,
                                  const float* __restrict__ w,
                                  const float* __restrict__ bb)
{
    const size_t base = (size_t)blockIdx.x * D_DIM;
    float4* yp = reinterpret_cast<float4*>(y + base);
    float4 v[2];
    float sum = 0.0f;
    #pragma unroll
    for (int i = 0; i < 2; i++) {
        v[i] = yp[threadIdx.x + 256 * i];
        sum += v[i].x + v[i].y + v[i].z + v[i].w;
    }
    float mu = block_reduce_sum(sum) * (1.0f / D_DIM);
    float sq = 0.0f;
    #pragma unroll
    for (int i = 0; i < 2; i++) {
        float dx = v[i].x - mu, dy = v[i].y - mu, dz = v[i].z - mu, dw = v[i].w - mu;
        sq += dx*dx + dy*dy + dz*dz + dw*dw;
    }
    float var = block_reduce_sum(sq) * (1.0f / D_DIM);
    float rstd = rsqrtf(var + 1e-5f);
    #pragma unroll
    for (int i = 0; i < 2; i++) {
        int col = (threadIdx.x + 256 * i) * 4;
        float4 wv = *reinterpret_cast<const float4*>(&w[col]);
        float4 bv = *reinterpret_cast<const float4*>(&bb[col]);
        float4 o;
        o.x = wv.x * (v[i].x - mu) * rstd + bv.x;
        o.y = wv.y * (v[i].y - mu) * rstd + bv.y;
        o.z = wv.z * (v[i].z - mu) * rstd + bv.z;
        o.w = wv.w * (v[i].w - mu) * rstd + bv.w;
        yp[threadIdx.x + 256 * i] = o;
    }
}

// ---------------------------------------------------------------------------
// Launch
// ---------------------------------------------------------------------------
extern "C" void kernel_launch(void* const* d_in, const int* in_sizes, int n_in,
                              void* d_out, int out_size)
{
    const float* x      = (const float*)d_in[0];
    const float* protos = (const float*)d_in[1];
    const float* conf   = (const float*)d_in[2];
    const float* age    = (const float*)d_in[3];
    const float* ev     = (const float*)d_in[4];
    const float* W_in   = (const float*)d_in[5];
    const float* b_in   = (const float*)d_in[6];
    const float* Wr1    = (const float*)d_in[7];
    const float* br1    = (const float*)d_in[8];
    const float* Wr2    = (const float*)d_in[9];
    const float* br2    = (const float*)d_in[10];
    const float* W_out  = (const float*)d_in[11];
    const float* b_out  = (const float*)d_in[12];
    const float* ln_w   = (const float*)d_in[13];
    const float* ln_b   = (const float*)d_in[14];
    float* out = (float*)d_out;

    __half *xh, *winh, *wr1h, *wcomb, *attnh;
    float *h, *r, *tw, *pn, *p2part;
    cudaGetSymbolAddress((void**)&xh,    g_x_h);
    cudaGetSymbolAddress((void**)&winh,  g_Win_h);
    cudaGetSymbolAddress((void**)&wr1h,  g_Wr1_h);
    cudaGetSymbolAddress((void**)&wcomb, g_wcomb);
    cudaGetSymbolAddress((void**)&attnh, g_attn_h);
    cudaGetSymbolAddress((void**)&p2part, g_p2part);
    cudaGetSymbolAddress((void**)&h,    g_h);
    cudaGetSymbolAddress((void**)&r,    g_r);
    cudaGetSymbolAddress((void**)&tw,   g_tw);
    cudaGetSymbolAddress((void**)&pn,   g_pn);

    constexpr int SMEM_SZ = 3 * 2 * 128 * 64 * 2;   // 98304 bytes
    cudaFuncSetAttribute(mma_gemm<8>, cudaFuncAttributeMaxDynamicSharedMemorySize, SMEM_SZ);
    cudaFuncSetAttribute(mma_gemm<7>, cudaFuncAttributeMaxDynamicSharedMemorySize, SMEM_SZ);

    const int B = B_ROWS;

    // fp16 conversions + combined W_out build
    {
        size_t n4;
        n4 = (size_t)B * D_DIM / 4;
        tohalf_kernel<<<(unsigned)((n4 + 255) / 256), 256>>>(x, xh, n4);
        n4 = (size_t)D_DIM * D_DIM / 4;
        tohalf_kernel<<<(unsigned)((n4 + 255) / 256), 256>>>(W_in, winh, n4);
        n4 = (size_t)D_HALF * D_DIM / 4;
        tohalf_kernel<<<(unsigned)((n4 + 255) / 256), 256>>>(Wr1, wr1h, n4);
        wout1_pack_kernel<<<(D_DIM * D_DIM / 4) / 256, 256>>>(W_out, wcomb);
        p2_kernel<<<dim3(D_DIM / 128, 4), 256>>>(protos, W_out, p2part);
        p2_reduce_kernel<<<(S_PROTO * D_DIM) / 256, 256>>>(p2part, wcomb);
    }

    proto_prep<<<S_PROTO, 256>>>(protos, conf, age, ev);

    // G1+G2 fused: h = x@W_in^T + b_in ; r = gelu(x@Wr1^T + br1)
    mma_gemm<8><<<dim3(D_DIM / 128 + D_HALF / 128, B / 128), 256, SMEM_SZ>>>(
        xh, nullptr, winh, b_in, nullptr, h,
        D_DIM, D_DIM, 0, D_DIM, 0,
        wr1h, br1, r, D_HALF, D_DIM / 128);

    type_weights_kernel<<<B / 8, 256>>>(r, Wr2, br2, tw);

    // fused rownorm + sim + salience + softmax -> attn (fp16)
    sim_attn_kernel<<<dim3(1, B / 128), 256, 33792>>>(h, pn, tw, attnh);

    // G3: out = gelu([x | attn] @ [W_out1 | P2]^T + b_out) + x    (K = 2112)
    mma_gemm<7><<<dim3(D_DIM / 128, B / 128), 256, SMEM_SZ>>>(
        xh, attnh, wcomb, b_out, x, out,
        D_DIM, KCOMB, D_DIM, D_DIM, S_PROTO,
        nullptr, nullptr, nullptr, 0, 0x7FFFFFFF);

    layernorm_inplace<<<B, 256>>>(out, ln_w, ln_b);
}

// round 8
// speedup vs baseline: 1.5813x; 1.1031x over previous
#include <cuda_runtime.h>
#include <cuda_fp16.h>
#include <math.h>
#include <stdint.h>

#define B_ROWS 16384
#define D_DIM  2048
#define D_HALF 1024
#define S_PROTO 64
#define KCOMB  (D_DIM + S_PROTO)   // 2112

// ---------------------------------------------------------------------------
// Scratch (device globals; allocation-free per harness rules)
// ---------------------------------------------------------------------------
__device__ __half g_x_h[(size_t)B_ROWS * D_DIM];
__device__ __half g_Win_h[(size_t)D_DIM * D_DIM];
__device__ __half g_Wr1_h[(size_t)D_HALF * D_DIM];
__device__ __half g_wcomb[(size_t)D_DIM * KCOMB];      // [W_out1 | P2^T] fp16
__device__ __half g_attn_h[(size_t)B_ROWS * S_PROTO];
__device__ __half g_h_h[(size_t)B_ROWS * D_DIM];       // h in fp16
__device__ __half g_r_h[(size_t)B_ROWS * D_HALF];      // r in fp16
__device__ __half g_pn_h[(size_t)S_PROTO * D_DIM];     // normalized protos fp16
__device__ float g_p2part[4 * S_PROTO * D_DIM];
__device__ float g_tw[(size_t)B_ROWS * 4];
__device__ float g_base[S_PROTO];
__device__ float g_wsimc[S_PROTO];

// ---------------------------------------------------------------------------
// PTX helpers (baseline ISA: mma.sync / ldmatrix / cp.async)
// ---------------------------------------------------------------------------
__device__ __forceinline__ uint32_t smem_to_u32(const void* p) {
    uint32_t a;
    asm("{ .reg .u64 t; cvta.to.shared.u64 t, %1; cvt.u32.u64 %0, t; }"
        : "=r"(a) : "l"(p));
    return a;
}

__device__ __forceinline__ void cpasync16(uint32_t saddr, const void* g) {
    asm volatile("cp.async.cg.shared.global [%0], [%1], 16;"
                 :: "r"(saddr), "l"(g));
}
#define CP_COMMIT() asm volatile("cp.async.commit_group;" ::: "memory")
#define CP_WAIT(n)  asm volatile("cp.async.wait_group %0;" :: "n"(n) : "memory")

__device__ __forceinline__ void ldsm4(uint32_t* r, uint32_t addr) {
    asm volatile("ldmatrix.sync.aligned.m8n8.x4.shared.b16 {%0,%1,%2,%3}, [%4];"
                 : "=r"(r[0]), "=r"(r[1]), "=r"(r[2]), "=r"(r[3]) : "r"(addr));
}

__device__ __forceinline__ void mma_f16(float* d, const uint32_t* a, const uint32_t* b) {
    asm volatile(
        "mma.sync.aligned.m16n8k16.row.col.f32.f16.f16.f32 "
        "{%0,%1,%2,%3}, {%4,%5,%6,%7}, {%8,%9}, {%0,%1,%2,%3};"
        : "+f"(d[0]), "+f"(d[1]), "+f"(d[2]), "+f"(d[3])
        : "r"(a[0]), "r"(a[1]), "r"(a[2]), "r"(a[3]), "r"(b[0]), "r"(b[1]));
}

// ---------------------------------------------------------------------------
// Misc helpers
// ---------------------------------------------------------------------------
__device__ __forceinline__ float gelu_exact(float v) {
    return 0.5f * v * (1.0f + erff(v * 0.70710678118654752440f));
}

__device__ __forceinline__ float block_reduce_sum(float v) {
    __shared__ float sh[32];
    int lane = threadIdx.x & 31, w = threadIdx.x >> 5;
    #pragma unroll
    for (int o = 16; o; o >>= 1) v += __shfl_xor_sync(0xFFFFFFFFu, v, o);
    if (lane == 0) sh[w] = v;
    __syncthreads();
    float r = (threadIdx.x < (blockDim.x >> 5)) ? sh[threadIdx.x] : 0.0f;
    if (w == 0) {
        #pragma unroll
        for (int o = 16; o; o >>= 1) r += __shfl_xor_sync(0xFFFFFFFFu, r, o);
        if (lane == 0) sh[0] = r;
    }
    __syncthreads();
    float out = sh[0];
    __syncthreads();
    return out;
}

// ---------------------------------------------------------------------------
// fp32 -> fp16 convert (vectorized, contiguous)
// ---------------------------------------------------------------------------
__global__ void tohalf_kernel(const float* __restrict__ s,
                              __half* __restrict__ d, size_t n4)
{
    size_t i = (size_t)blockIdx.x * blockDim.x + threadIdx.x;
    if (i >= n4) return;
    float4 v = reinterpret_cast<const float4*>(s)[i];
    __half2 h0 = __floats2half2_rn(v.x, v.y);
    __half2 h1 = __floats2half2_rn(v.z, v.w);
    uint2 o;
    o.x = *reinterpret_cast<uint32_t*>(&h0);
    o.y = *reinterpret_cast<uint32_t*>(&h1);
    reinterpret_cast<uint2*>(d)[i] = o;
}

// ---------------------------------------------------------------------------
// Pack W_out[:, 0:2048] (stride 4096) into wcomb[:, 0:2048] (stride 2112) fp16
// ---------------------------------------------------------------------------
__global__ void wout1_pack_kernel(const float* __restrict__ wout,
                                  __half* __restrict__ wcomb)
{
    int idx = blockIdx.x * 256 + threadIdx.x;
    int row = idx >> 9;
    int c4  = idx & 511;
    float4 v = *reinterpret_cast<const float4*>(wout + (size_t)row * 2 * D_DIM + c4 * 4);
    __half2 h0 = __floats2half2_rn(v.x, v.y);
    __half2 h1 = __floats2half2_rn(v.z, v.w);
    uint2 o;
    o.x = *reinterpret_cast<uint32_t*>(&h0);
    o.y = *reinterpret_cast<uint32_t*>(&h1);
    *reinterpret_cast<uint2*>(wcomb + (size_t)row * KCOMB + c4 * 4) = o;
}

// ---------------------------------------------------------------------------
// P2 partials (k-split, conflict-free transposed tiles)
// ---------------------------------------------------------------------------
__global__ void __launch_bounds__(256)
p2_kernel(const float* __restrict__ protos, const float* __restrict__ wout,
          float* __restrict__ part)
{
    constexpr int BKC = 32;
    __shared__ float Pt[BKC][68];
    __shared__ float Wt[BKC][132];

    const int tid = threadIdx.x;
    const int n0 = blockIdx.x * 128;
    const int kb = blockIdx.y * 512;
    const int tr = tid >> 4;
    const int tc = tid & 15;

    float acc[4][8];
    #pragma unroll
    for (int i = 0; i < 4; i++)
        #pragma unroll
        for (int j = 0; j < 8; j++) acc[i][j] = 0.0f;

    for (int kt = 0; kt < 512; kt += BKC) {
        #pragma unroll
        for (int i = 0; i < 2; i++) {
            int idx = tid + i * 256;
            int s = idx >> 3, kq = (idx & 7) * 4;
            float4 v = *reinterpret_cast<const float4*>(
                protos + (size_t)s * D_DIM + kb + kt + kq);
            Pt[kq+0][s] = v.x; Pt[kq+1][s] = v.y;
            Pt[kq+2][s] = v.z; Pt[kq+3][s] = v.w;
        }
        #pragma unroll
        for (int i = 0; i < 4; i++) {
            int idx = tid + i * 256;
            int n = idx >> 3, kq = (idx & 7) * 4;
            float4 v = *reinterpret_cast<const float4*>(
                wout + (size_t)(n0 + n) * 2 * D_DIM + D_DIM + kb + kt + kq);
            Wt[kq+0][n] = v.x; Wt[kq+1][n] = v.y;
            Wt[kq+2][n] = v.z; Wt[kq+3][n] = v.w;
        }
        __syncthreads();
        #pragma unroll 8
        for (int k = 0; k < BKC; k++) {
            float4 p  = *reinterpret_cast<const float4*>(&Pt[k][tr * 4]);
            float4 wa = *reinterpret_cast<const float4*>(&Wt[k][tc * 8]);
            float4 wb = *reinterpret_cast<const float4*>(&Wt[k][tc * 8 + 4]);
            float pv[4] = {p.x, p.y, p.z, p.w};
            float wv[8] = {wa.x, wa.y, wa.z, wa.w, wb.x, wb.y, wb.z, wb.w};
            #pragma unroll
            for (int i = 0; i < 4; i++)
                #pragma unroll
                for (int j = 0; j < 8; j++)
                    acc[i][j] = fmaf(pv[i], wv[j], acc[i][j]);
        }
        __syncthreads();
    }

    float* dst = part + (size_t)blockIdx.y * S_PROTO * D_DIM;
    #pragma unroll
    for (int i = 0; i < 4; i++)
        #pragma unroll
        for (int j = 0; j < 8; j++)
            dst[(size_t)(tr * 4 + i) * D_DIM + n0 + tc * 8 + j] = acc[i][j];
}

__global__ void p2_reduce_kernel(const float* __restrict__ part,
                                 __half* __restrict__ wcomb)
{
    int idx = blockIdx.x * 256 + threadIdx.x;
    int s = idx >> 11;
    int n = idx & 2047;
    size_t o = (size_t)s * D_DIM + n;
    float v = part[o] + part[o + S_PROTO * D_DIM]
            + part[o + 2 * S_PROTO * D_DIM] + part[o + 3 * S_PROTO * D_DIM];
    wcomb[(size_t)n * KCOMB + D_DIM + s] = __float2half_rn(v);
}

// ---------------------------------------------------------------------------
// Single-pass fp16 HMMA GEMM.
// MODE bits: 1=gelu, 2=+Xres(fp32), 4=split-A, 8=dual-output (second gelued),
//            16=fp16 outputs (both C and C2).
// BM=BN=128, BK=64, 3-stage cp.async, 256 threads, 2 CTAs/SM.
// ---------------------------------------------------------------------------
template<int MODE>
__global__ void __launch_bounds__(256, 2)
mma_gemm(const __half* __restrict__ A, const __half* __restrict__ A2,
         const __half* __restrict__ Bm,
         const float* __restrict__ bias, const float* __restrict__ Xres,
         void* __restrict__ C, int N, int K, int Ksplit,
         int strideA, int strideA2,
         const __half* __restrict__ B2,
         const float* __restrict__ bias2, void* __restrict__ C2,
         int N2, int NXtiles)
{
    constexpr int BM = 128, BK = 64, STAGES = 3;
    constexpr int TILE_B  = BM * BK * 2;
    constexpr int STAGE_B = 2 * TILE_B;

    extern __shared__ __align__(16) char smem[];
    const uint32_t sbase = smem_to_u32(smem);

    const int tid  = threadIdx.x;
    const int wid  = tid >> 5, lane = tid & 31;
    const int m0 = blockIdx.y * BM;

    int bx = blockIdx.x;
    bool second = false;
    if constexpr (MODE & 8) {
        if (bx >= NXtiles) { second = true; bx -= NXtiles; }
    }
    const __half* pB = second ? B2 : Bm;
    const float* pbias = second ? bias2 : bias;
    void* pC = second ? C2 : C;
    const int NN = second ? N2 : N;
    const int n0 = bx * BM;
    const bool do_gelu = (MODE & 1) || second;

    const int wm = (wid >> 2) * 64;
    const int wn = (wid & 3) * 32;

    float acc[4][4][4];
    #pragma unroll
    for (int i = 0; i < 4; i++)
        #pragma unroll
        for (int j = 0; j < 4; j++)
            #pragma unroll
            for (int k = 0; k < 4; k++) acc[i][j][k] = 0.0f;

    const int nk = K / BK;

    auto load_stage = [&](int s, int t) {
        const int k0 = t * BK;
        const __half* pA = A;
        int ka = k0, sA = strideA;
        if constexpr (MODE & 4) {
            if (k0 >= Ksplit) { pA = A2; ka = k0 - Ksplit; sA = strideA2; }
        }
        const uint32_t sb = sbase + s * STAGE_B;
        #pragma unroll
        for (int i = 0; i < 4; i++) {
            int idx = tid + i * 256;
            int row = idx >> 3, g = idx & 7;
            int gs  = g ^ (row & 7);
            uint32_t so = row * 128 + gs * 16;
            size_t ga = (size_t)(m0 + row) * sA + ka + g * 8;
            size_t gb = (size_t)(n0 + row) * K + k0 + g * 8;
            cpasync16(sb + so, pA + ga);
            cpasync16(sb + TILE_B + so, pB + gb);
        }
    };

    auto compute_stage = [&](int s) {
        const uint32_t sb = sbase + s * STAGE_B;
        #pragma unroll
        for (int ks = 0; ks < 4; ks++) {
            uint32_t afr[4][4], bfr[2][4];
            #pragma unroll
            for (int mf = 0; mf < 4; mf++) {
                int row = wm + mf * 16 + (lane & 15);
                int g   = ks * 2 + (lane >> 4);
                ldsm4(afr[mf], sb + row * 128 + ((g ^ (row & 7)) * 16));
            }
            #pragma unroll
            for (int nf2 = 0; nf2 < 2; nf2++) {
                int nrow = wn + nf2 * 16 + ((lane >> 4) & 1) * 8 + (lane & 7);
                int g    = ks * 2 + ((lane >> 3) & 1);
                ldsm4(bfr[nf2], sb + TILE_B + nrow * 128 + ((g ^ (nrow & 7)) * 16));
            }
            #pragma unroll
            for (int mf = 0; mf < 4; mf++)
                #pragma unroll
                for (int nf = 0; nf < 4; nf++)
                    mma_f16(acc[mf][nf], afr[mf], &bfr[nf >> 1][(nf & 1) * 2]);
        }
    };

    load_stage(0, 0); CP_COMMIT();
    load_stage(1, 1); CP_COMMIT();

    for (int t = 0; t < nk; t++) {
        CP_WAIT(STAGES - 2);
        __syncthreads();
        if (t + STAGES - 1 < nk) load_stage((t + STAGES - 1) % STAGES, t + STAGES - 1);
        CP_COMMIT();
        compute_stage(t % STAGES);
    }

    #pragma unroll
    for (int mf = 0; mf < 4; mf++)
        #pragma unroll
        for (int nf = 0; nf < 4; nf++)
            #pragma unroll
            for (int half = 0; half < 2; half++) {
                int row = m0 + wm + mf * 16 + (lane >> 2) + half * 8;
                int col = n0 + wn + nf * 8 + (lane & 3) * 2;
                float v0 = acc[mf][nf][half * 2 + 0] + pbias[col];
                float v1 = acc[mf][nf][half * 2 + 1] + pbias[col + 1];
                if (do_gelu) { v0 = gelu_exact(v0); v1 = gelu_exact(v1); }
                if constexpr (MODE & 2) {
                    float2 xr = *reinterpret_cast<const float2*>(
                        &Xres[(size_t)row * NN + col]);
                    v0 += xr.x; v1 += xr.y;
                }
                if constexpr (MODE & 16) {
                    __half2 o = __floats2half2_rn(v0, v1);
                    *reinterpret_cast<__half2*>(
                        (__half*)pC + (size_t)row * NN + col) = o;
                } else {
                    float2 o; o.x = v0; o.y = v1;
                    *reinterpret_cast<float2*>(
                        (float*)pC + (size_t)row * NN + col) = o;
                }
            }
}

// ---------------------------------------------------------------------------
// sim_attn v2: HMMA sim (fp16 h @ fp16 pn^T) + in-flight ssq + salience
// + softmax -> attn fp16. BM=128 rows/block, 256 threads (8 warps, 16 rows ea).
// ---------------------------------------------------------------------------
__global__ void __launch_bounds__(256)
sim_attn_kernel(const __half* __restrict__ H, const __half* __restrict__ PN,
                const float* __restrict__ tw, __half* __restrict__ attn)
{
    constexpr int BK = 64;
    constexpr int H_B  = 128 * BK * 2;     // 16384
    constexpr int PN_B = S_PROTO * BK * 2; // 8192
    constexpr int STAGE_B = H_B + PN_B;    // 24576
    constexpr int SSQ_OFF = 2 * STAGE_B;   // 49152

    extern __shared__ __align__(16) char dsm[];
    const uint32_t sbase = smem_to_u32(dsm);
    float* sal = reinterpret_cast<float*>(dsm);
    float* ssq_sm = reinterpret_cast<float*>(dsm + SSQ_OFF);

    const int tid = threadIdx.x;
    const int wid = tid >> 5, lane = tid & 31;
    const int m0 = blockIdx.x * 128;
    const int K = D_DIM;

    float acc[8][4];
    #pragma unroll
    for (int i = 0; i < 8; i++)
        #pragma unroll
        for (int j = 0; j < 4; j++) acc[i][j] = 0.0f;

    uint4 hReg[4]; uint4 pReg[2];
    float ssq[4] = {0.f, 0.f, 0.f, 0.f};

    auto fetch = [&](int t) {
        const int k0 = t * BK;
        #pragma unroll
        for (int i = 0; i < 4; i++) {
            int idx = tid + i * 256;
            int row = idx >> 3, g = idx & 7;
            hReg[i] = *reinterpret_cast<const uint4*>(
                H + (size_t)(m0 + row) * K + k0 + g * 8);
            // ssq from the 8 halves
            #pragma unroll
            for (int q = 0; q < 4; q++) {
                __half2 hv = *reinterpret_cast<__half2*>(
                    reinterpret_cast<uint32_t*>(&hReg[i]) + q);
                float2 f = __half22float2(hv);
                ssq[i] += f.x * f.x + f.y * f.y;
            }
        }
        #pragma unroll
        for (int i = 0; i < 2; i++) {
            int idx = tid + i * 256;
            int s = idx >> 3, g = idx & 7;
            pReg[i] = *reinterpret_cast<const uint4*>(
                PN + (size_t)s * K + k0 + g * 8);
        }
    };
    auto stash = [&](int buf) {
        const uint32_t sb = sbase + buf * STAGE_B;
        char* cb = dsm + buf * STAGE_B;
        #pragma unroll
        for (int i = 0; i < 4; i++) {
            int idx = tid + i * 256;
            int row = idx >> 3, g = idx & 7;
            *reinterpret_cast<uint4*>(cb + row * 128 + ((g ^ (row & 7)) * 16)) = hReg[i];
        }
        #pragma unroll
        for (int i = 0; i < 2; i++) {
            int idx = tid + i * 256;
            int s = idx >> 3, g = idx & 7;
            *reinterpret_cast<uint4*>(cb + H_B + s * 128 + ((g ^ (s & 7)) * 16)) = pReg[i];
        }
        (void)sb;
    };
    auto compute = [&](int buf) {
        const uint32_t sb = sbase + buf * STAGE_B;
        #pragma unroll
        for (int ks = 0; ks < 4; ks++) {
            uint32_t afr[4], bfr[4][4];
            {
                int row = wid * 16 + (lane & 15);
                int g   = ks * 2 + (lane >> 4);
                ldsm4(afr, sb + row * 128 + ((g ^ (row & 7)) * 16));
            }
            #pragma unroll
            for (int nf2 = 0; nf2 < 4; nf2++) {
                int nrow = nf2 * 16 + ((lane >> 4) & 1) * 8 + (lane & 7);
                int g    = ks * 2 + ((lane >> 3) & 1);
                ldsm4(bfr[nf2], sb + H_B + nrow * 128 + ((g ^ (nrow & 7)) * 16));
            }
            #pragma unroll
            for (int nf = 0; nf < 8; nf++)
                mma_f16(acc[nf], afr, &bfr[nf >> 1][(nf & 1) * 2]);
        }
    };

    const int nk = K / BK;   // 32
    fetch(0); stash(0);
    __syncthreads();
    for (int t = 0; t < nk; t++) {
        const int cur = t & 1;
        if (t + 1 < nk) fetch(t + 1);
        compute(cur);
        if (t + 1 < nk) stash(cur ^ 1);
        __syncthreads();
    }

    // reduce ssq: rows r_i = (tid>>3) + 32*i; 8 consecutive tids share a row
    #pragma unroll
    for (int i = 0; i < 4; i++) {
        ssq[i] += __shfl_xor_sync(0xFFFFFFFFu, ssq[i], 1);
        ssq[i] += __shfl_xor_sync(0xFFFFFFFFu, ssq[i], 2);
        ssq[i] += __shfl_xor_sync(0xFFFFFFFFu, ssq[i], 4);
    }
    if ((tid & 7) == 0) {
        #pragma unroll
        for (int i = 0; i < 4; i++) ssq_sm[(tid >> 3) + 32 * i] = ssq[i];
    }
    __syncthreads();   // ssq ready; smem buffers free -> overlay sal

    // salience into smem
    {
        int r0 = wid * 16 + (lane >> 2);
        #pragma unroll
        for (int half = 0; half < 2; half++) {
            int row = r0 + half * 8;
            float invn = 1.0f / fmaxf(sqrtf(ssq_sm[row]), 1e-12f);
            #pragma unroll
            for (int nf = 0; nf < 8; nf++) {
                int col = nf * 8 + (lane & 3) * 2;
                float twv = tw[(size_t)(m0 + row) * 4 + (col >> 4)];
                float v0 = g_wsimc[col] * twv * (acc[nf][half*2+0] * invn) + g_base[col];
                float twv1 = tw[(size_t)(m0 + row) * 4 + ((col + 1) >> 4)];
                float v1 = g_wsimc[col+1] * twv1 * (acc[nf][half*2+1] * invn) + g_base[col+1];
                sal[row * 65 + col]     = fminf(fmaxf(v0, 0.0f), 1.0f);
                sal[row * 65 + col + 1] = fminf(fmaxf(v1, 0.0f), 1.0f);
            }
        }
    }
    __syncthreads();

    // softmax over 64 per row; 2 threads per row
    {
        int row = tid >> 1, half = tid & 1;
        const float* srow = &sal[row * 65 + half * 32];
        float m = -1e30f;
        #pragma unroll
        for (int c = 0; c < 32; c++) m = fmaxf(m, srow[c]);
        m = fmaxf(m, __shfl_xor_sync(0xFFFFFFFFu, m, 1));
        const float invT = 1.0f / 0.07f;
        float e[32], s = 0.0f;
        #pragma unroll
        for (int c = 0; c < 32; c++) { e[c] = expf((srow[c] - m) * invT); s += e[c]; }
        s += __shfl_xor_sync(0xFFFFFFFFu, s, 1);
        float inv = 1.0f / s;
        __half* dst = &attn[(size_t)(m0 + row) * S_PROTO + half * 32];
        #pragma unroll
        for (int c = 0; c < 32; c += 2) {
            __half2 o = __floats2half2_rn(e[c] * inv, e[c+1] * inv);
            *reinterpret_cast<__half2*>(dst + c) = o;
        }
    }
}

// ---------------------------------------------------------------------------
// Prototype prep: normalized protos -> fp16, plus static salience terms
// ---------------------------------------------------------------------------
__global__ void proto_prep(const float* __restrict__ protos,
                           const float* __restrict__ conf,
                           const float* __restrict__ age,
                           const float* __restrict__ ev,
                           __half* __restrict__ pn_h)
{
    const int s = blockIdx.x;
    float ss = 0.0f;
    for (int k = threadIdx.x; k < D_DIM; k += 256) {
        float v = protos[(size_t)s * D_DIM + k];
        ss += v * v;
    }
    float tot = block_reduce_sum(ss);
    float scale = 1.0f / fmaxf(sqrtf(tot), 1e-12f);
    for (int k = threadIdx.x; k < D_DIM; k += 256)
        pn_h[(size_t)s * D_DIM + k] =
            __float2half_rn(protos[(size_t)s * D_DIM + k] * scale);

    if (threadIdx.x == 0) {
        float evmax = 0.0f;
        for (int i = 0; i < S_PROTO; i++) evmax = fmaxf(evmax, ev[i]);
        float freq = logf(ev[s] + 1.0f) / (logf(evmax + 2.0f) + 1e-8f);
        float rec  = expf(-age[s] * (1.0f / 200.0f));
        g_base[s]  = 0.2f * rec + 0.15f * freq + 0.1f * conf[s] + 0.1f * 0.9f;
        g_wsimc[s] = 0.45f * conf[s];
    }
}

// ---------------------------------------------------------------------------
// Type weights softmax (4 logits), r in fp16. 1 warp per row.
// ---------------------------------------------------------------------------
__global__ void type_weights_kernel(const __half* __restrict__ r,
                                    const float* __restrict__ Wr2,
                                    const float* __restrict__ br2,
                                    float* __restrict__ tw)
{
    const int warp = threadIdx.x >> 5, lane = threadIdx.x & 31;
    const int b = blockIdx.x * 8 + warp;
    const uint4* rp = reinterpret_cast<const uint4*>(r + (size_t)b * D_HALF);
    float acc[4] = {0.f, 0.f, 0.f, 0.f};
    for (int i = lane; i < D_HALF / 8; i += 32) {
        uint4 rv = rp[i];
        float rf[8];
        #pragma unroll
        for (int q = 0; q < 4; q++) {
            __half2 hv = *reinterpret_cast<__half2*>(
                reinterpret_cast<uint32_t*>(&rv) + q);
            float2 f = __half22float2(hv);
            rf[q*2] = f.x; rf[q*2+1] = f.y;
        }
        #pragma unroll
        for (int t = 0; t < 4; t++) {
            const float* wr = Wr2 + (size_t)t * D_HALF + i * 8;
            float4 w0 = *reinterpret_cast<const float4*>(wr);
            float4 w1 = *reinterpret_cast<const float4*>(wr + 4);
            acc[t] += rf[0]*w0.x + rf[1]*w0.y + rf[2]*w0.z + rf[3]*w0.w
                    + rf[4]*w1.x + rf[5]*w1.y + rf[6]*w1.z + rf[7]*w1.w;
        }
    }
    #pragma unroll
    for (int t = 0; t < 4; t++)
        #pragma unroll
        for (int o = 16; o; o >>= 1)
            acc[t] += __shfl_xor_sync(0xFFFFFFFFu, acc[t], o);
    if (lane == 0) {
        float z[4], m = -1e30f;
        #pragma unroll
        for (int t = 0; t < 4; t++) { z[t] = acc[t] + br2[t]; m = fmaxf(m, z[t]); }
        float s = 0.0f;
        #pragma unroll
        for (int t = 0; t < 4; t++) { z[t] = expf(z[t] - m); s += z[t]; }
        float inv = 1.0f / s;
        #pragma unroll
        for (int t = 0; t < 4; t++) tw[(size_t)b * 4 + t] = z[t] * inv;
    }
}

// ---------------------------------------------------------------------------
// In-place LayerNorm over D
// ---------------------------------------------------------------------------
__global__ void layernorm_inplace(float* __restrict__ y,
                                  const float* __restrict__ w,
                                  const float* __restrict__ bb)
{
    const size_t base = (size_t)blockIdx.x * D_DIM;
    float4* yp = reinterpret_cast<float4*>(y + base);
    float4 v[2];
    float sum = 0.0f;
    #pragma unroll
    for (int i = 0; i < 2; i++) {
        v[i] = yp[threadIdx.x + 256 * i];
        sum += v[i].x + v[i].y + v[i].z + v[i].w;
    }
    float mu = block_reduce_sum(sum) * (1.0f / D_DIM);
    float sq = 0.0f;
    #pragma unroll
    for (int i = 0; i < 2; i++) {
        float dx = v[i].x - mu, dy = v[i].y - mu, dz = v[i].z - mu, dw = v[i].w - mu;
        sq += dx*dx + dy*dy + dz*dz + dw*dw;
    }
    float var = block_reduce_sum(sq) * (1.0f / D_DIM);
    float rstd = rsqrtf(var + 1e-5f);
    #pragma unroll
    for (int i = 0; i < 2; i++) {
        int col = (threadIdx.x + 256 * i) * 4;
        float4 wv = *reinterpret_cast<const float4*>(&w[col]);
        float4 bv = *reinterpret_cast<const float4*>(&bb[col]);
        float4 o;
        o.x = wv.x * (v[i].x - mu) * rstd + bv.x;
        o.y = wv.y * (v[i].y - mu) * rstd + bv.y;
        o.z = wv.z * (v[i].z - mu) * rstd + bv.z;
        o.w = wv.w * (v[i].w - mu) * rstd + bv.w;
        yp[threadIdx.x + 256 * i] = o;
    }
}

// ---------------------------------------------------------------------------
// Launch
// ---------------------------------------------------------------------------
extern "C" void kernel_launch(void* const* d_in, const int* in_sizes, int n_in,
                              void* d_out, int out_size)
{
    const float* x      = (const float*)d_in[0];
    const float* protos = (const float*)d_in[1];
    const float* conf   = (const float*)d_in[2];
    const float* age    = (const float*)d_in[3];
    const float* ev     = (const float*)d_in[4];
    const float* W_in   = (const float*)d_in[5];
    const float* b_in   = (const float*)d_in[6];
    const float* Wr1    = (const float*)d_in[7];
    const float* br1    = (const float*)d_in[8];
    const float* Wr2    = (const float*)d_in[9];
    const float* br2    = (const float*)d_in[10];
    const float* W_out  = (const float*)d_in[11];
    const float* b_out  = (const float*)d_in[12];
    const float* ln_w   = (const float*)d_in[13];
    const float* ln_b   = (const float*)d_in[14];
    float* out = (float*)d_out;

    __half *xh, *winh, *wr1h, *wcomb, *attnh, *hh, *rh, *pnh;
    float *tw, *p2part;
    cudaGetSymbolAddress((void**)&xh,    g_x_h);
    cudaGetSymbolAddress((void**)&winh,  g_Win_h);
    cudaGetSymbolAddress((void**)&wr1h,  g_Wr1_h);
    cudaGetSymbolAddress((void**)&wcomb, g_wcomb);
    cudaGetSymbolAddress((void**)&attnh, g_attn_h);
    cudaGetSymbolAddress((void**)&hh,    g_h_h);
    cudaGetSymbolAddress((void**)&rh,    g_r_h);
    cudaGetSymbolAddress((void**)&pnh,   g_pn_h);
    cudaGetSymbolAddress((void**)&p2part, g_p2part);
    cudaGetSymbolAddress((void**)&tw,    g_tw);

    constexpr int SMEM_SZ = 3 * 2 * 128 * 64 * 2;   // 98304
    constexpr int SIM_SMEM = 49152 + 640;           // buffers + ssq
    cudaFuncSetAttribute(mma_gemm<24>, cudaFuncAttributeMaxDynamicSharedMemorySize, SMEM_SZ);
    cudaFuncSetAttribute(mma_gemm<7>,  cudaFuncAttributeMaxDynamicSharedMemorySize, SMEM_SZ);
    cudaFuncSetAttribute(sim_attn_kernel, cudaFuncAttributeMaxDynamicSharedMemorySize, SIM_SMEM);

    const int B = B_ROWS;

    // fp16 conversions + combined W_out build
    {
        size_t n4;
        n4 = (size_t)B * D_DIM / 4;
        tohalf_kernel<<<(unsigned)((n4 + 255) / 256), 256>>>(x, xh, n4);
        n4 = (size_t)D_DIM * D_DIM / 4;
        tohalf_kernel<<<(unsigned)((n4 + 255) / 256), 256>>>(W_in, winh, n4);
        n4 = (size_t)D_HALF * D_DIM / 4;
        tohalf_kernel<<<(unsigned)((n4 + 255) / 256), 256>>>(Wr1, wr1h, n4);
        wout1_pack_kernel<<<(D_DIM * D_DIM / 4) / 256, 256>>>(W_out, wcomb);
        p2_kernel<<<dim3(D_DIM / 128, 4), 256>>>(protos, W_out, p2part);
        p2_reduce_kernel<<<(S_PROTO * D_DIM) / 256, 256>>>(p2part, wcomb);
    }

    proto_prep<<<S_PROTO, 256>>>(protos, conf, age, ev, pnh);

    // G1+G2 fused (fp16 outputs): h = x@W_in^T + b_in ; r = gelu(x@Wr1^T + br1)
    mma_gemm<24><<<dim3(D_DIM / 128 + D_HALF / 128, B / 128), 256, SMEM_SZ>>>(
        xh, nullptr, winh, b_in, nullptr, hh,
        D_DIM, D_DIM, 0, D_DIM, 0,
        wr1h, br1, rh, D_HALF, D_DIM / 128);

    type_weights_kernel<<<B / 8, 256>>>(rh, Wr2, br2, tw);

    // fused rownorm + HMMA sim + salience + softmax -> attn (fp16)
    sim_attn_kernel<<<B / 128, 256, SIM_SMEM>>>(hh, pnh, tw, attnh);

    // G3: out = gelu([x | attn] @ [W_out1 | P2]^T + b_out) + x    (K = 2112)
    mma_gemm<7><<<dim3(D_DIM / 128, B / 128), 256, SMEM_SZ>>>(
        xh, attnh, wcomb, b_out, x, out,
        D_DIM, KCOMB, D_DIM, D_DIM, S_PROTO,
        nullptr, nullptr, nullptr, 0, 0x7FFFFFFF);

    layernorm_inplace<<<B, 256>>>(out, ln_w, ln_b);
}